// round 1
// baseline (speedup 1.0000x reference)
#include <cuda_runtime.h>
#include <math.h>

#define B 64
#define T 512
#define E 256
#define U 256
#define Z 1024 /* 4*U */

// Segment storage: h1 value after each "active" step, piecewise-constant output.
// Worst case (all tokens == 0): T+1 segments per batch.
__device__ float g_seg_h[B][T + 1][U];
__device__ int   g_seg_t[B][T + 2];
__device__ int   g_nseg[B];

__device__ __forceinline__ float sigm(float v) { return 1.0f / (1.0f + expf(-v)); }

// Phase A: one CTA per batch. Scan tokens; only at positions where x==0 does the
// masked LSTM update state (Keras masked semantics: mask True == x==0 here).
// Each active step: z0 = (emb[0]@k0 + b0) + h0@r0 ; update (h0,c0);
//                   z1 = h0@k1 + b1 + h1@r1     ; update (h1,c1);
// record (t, h1) as a new output segment. Everything fp32, matching reference.
__global__ void lstm_active_kernel(const int*   __restrict__ x,
                                   const float* __restrict__ emb,
                                   const float* __restrict__ k0,
                                   const float* __restrict__ r0,
                                   const float* __restrict__ b0,
                                   const float* __restrict__ k1,
                                   const float* __restrict__ r1,
                                   const float* __restrict__ b1,
                                   float*       __restrict__ out)
{
    __shared__ float h0s[U];
    __shared__ float h1s[U];
    __shared__ unsigned char act[T];
    __shared__ int s_nact;

    const int b = blockIdx.x;
    const int j = threadIdx.x;   // unit index 0..255 (thread j owns unit j)

    if (j == 0) s_nact = 0;
    __syncthreads();

    // Stage the mask for this batch row.
    int localact = 0;
    for (int t = j; t < T; t += U) {
        int a = (x[b * T + t] == 0) ? 1 : 0;
        act[t] = (unsigned char)a;
        localact += a;
    }
    if (localact) atomicAdd(&s_nact, localact);

    h0s[j] = 0.0f;
    h1s[j] = 0.0f;
    float c0 = 0.0f, c1 = 0.0f;
    float h1r = 0.0f;            // local copy of h1s[j]

    // Segment 0: h1 == 0 starting at t = 0.
    g_seg_h[b][0][j] = 0.0f;
    if (j == 0) { g_seg_t[b][0] = 0; g_nseg[b] = 1; }
    __syncthreads();

    const int nact = s_nact;

    // Precompute constant layer-0 x-contribution: xzc = emb[0,:] @ k0 + b0.
    // Only needed if this batch has any active step. Thread j handles the 4 gate
    // columns of unit j: col = g*U + j (Keras split order i,f,g,o).
    float xzc0 = 0.f, xzc1 = 0.f, xzc2 = 0.f, xzc3 = 0.f;
    if (nact > 0) {
        float a0 = b0[0 * U + j], a1 = b0[1 * U + j];
        float a2 = b0[2 * U + j], a3 = b0[3 * U + j];
        for (int e = 0; e < E; e++) {
            const float ev = emb[e];             // emb row 0 (token 0)
            const float* kr = k0 + (size_t)e * Z;
            a0 += ev * kr[0 * U + j];
            a1 += ev * kr[1 * U + j];
            a2 += ev * kr[2 * U + j];
            a3 += ev * kr[3 * U + j];
        }
        xzc0 = a0; xzc1 = a1; xzc2 = a2; xzc3 = a3;
    }

    int nseg = 1;
    if (nact > 0) {
        for (int t = 0; t < T; t++) {
            if (!act[t]) continue;               // uniform across the block

            // ---- layer 0 recurrent matvec: z = xzc + h0 @ r0 ----
            float z0 = xzc0, z1 = xzc1, z2 = xzc2, z3 = xzc3;
            #pragma unroll 4
            for (int k = 0; k < U; k++) {
                const float hv = h0s[k];
                const float* rr = r0 + (size_t)k * Z;
                z0 += hv * rr[0 * U + j];
                z1 += hv * rr[1 * U + j];
                z2 += hv * rr[2 * U + j];
                z3 += hv * rr[3 * U + j];
            }
            __syncthreads();                     // all h0s reads done
            {
                const float ig = sigm(z0);
                const float fg = sigm(z1);
                const float gg = tanhf(z2);
                const float og = sigm(z3);
                c0 = fg * c0 + ig * gg;
                h0s[j] = og * tanhf(c0);         // mask is true here by construction
            }
            __syncthreads();                     // updated h0 visible (== out0[b,t])

            // ---- layer 1: z = h0 @ k1 + b1 + h1 @ r1 ----
            float w0 = b1[0 * U + j], w1 = b1[1 * U + j];
            float w2 = b1[2 * U + j], w3 = b1[3 * U + j];
            #pragma unroll 4
            for (int k = 0; k < U; k++) {
                const float hv = h0s[k];
                const float* kr = k1 + (size_t)k * Z;
                w0 += hv * kr[0 * U + j];
                w1 += hv * kr[1 * U + j];
                w2 += hv * kr[2 * U + j];
                w3 += hv * kr[3 * U + j];
            }
            #pragma unroll 4
            for (int k = 0; k < U; k++) {
                const float hv = h1s[k];
                const float* rr = r1 + (size_t)k * Z;
                w0 += hv * rr[0 * U + j];
                w1 += hv * rr[1 * U + j];
                w2 += hv * rr[2 * U + j];
                w3 += hv * rr[3 * U + j];
            }
            __syncthreads();                     // all h1s reads done
            {
                const float ig = sigm(w0);
                const float fg = sigm(w1);
                const float gg = tanhf(w2);
                const float og = sigm(w3);
                c1 = fg * c1 + ig * gg;
                h1r = og * tanhf(c1);
                h1s[j] = h1r;
            }
            __syncthreads();

            // Record new output segment starting at t.
            g_seg_h[b][nseg][j] = h1r;
            if (j == 0) g_seg_t[b][nseg] = t;
            nseg++;
        }
    }
    if (j == 0) g_nseg[b] = nseg;

    // Final hidden state output region: out[B*T*U + b*U + j]
    out[(size_t)B * T * U + (size_t)b * U + j] = h1r;
}

// Phase B: fill out[b,t,:] from the piecewise-constant segment table.
// grid = B * (T/64) CTAs, 256 threads. Each CTA writes a 64-timestep chunk
// (64 * 256 floats = 64 KB) with float4 stores.
__global__ void fill_out_kernel(float* __restrict__ out)
{
    const int b     = blockIdx.x >> 3;   // 8 chunks of 64 timesteps per batch
    const int chunk = blockIdx.x & 7;
    const int t0    = chunk * 64;

    __shared__ int segt[T + 2];
    __shared__ int s_n;

    const int tid = threadIdx.x;
    if (tid == 0) s_n = g_nseg[b];
    __syncthreads();
    const int n = s_n;
    for (int i = tid; i < n; i += 256) segt[i] = g_seg_t[b][i];
    __syncthreads();

    const int tr = tid >> 6;             // 0..3 : timestep within group of 4
    const int u4 = (tid & 63) * 4;       // 0..252 : unit (float4 granularity)

    for (int tt = 0; tt < 64; tt += 4) {
        const int t = t0 + tt + tr;
        // last segment index i with segt[i] <= t  (n is tiny; binary search)
        int lo = 0, hi = n - 1;
        while (lo < hi) {
            const int mid = (lo + hi + 1) >> 1;
            if (segt[mid] <= t) lo = mid; else hi = mid - 1;
        }
        const float4 v = *reinterpret_cast<const float4*>(&g_seg_h[b][lo][u4]);
        *reinterpret_cast<float4*>(&out[(size_t)b * T * U + (size_t)t * U + u4]) = v;
    }
}

extern "C" void kernel_launch(void* const* d_in, const int* in_sizes, int n_in,
                              void* d_out, int out_size)
{
    const int*   x   = (const int*)  d_in[0];
    const float* emb = (const float*)d_in[1];
    const float* k0  = (const float*)d_in[2];
    const float* r0  = (const float*)d_in[3];
    const float* b0  = (const float*)d_in[4];
    const float* k1  = (const float*)d_in[5];
    const float* r1  = (const float*)d_in[6];
    const float* b1  = (const float*)d_in[7];
    float* out = (float*)d_out;

    lstm_active_kernel<<<B, 256>>>(x, emb, k0, r0, b0, k1, r1, b1, out);
    fill_out_kernel<<<B * (T / 64), 256>>>(out);
}

// round 2
// speedup vs baseline: 1.2119x; 1.2119x over previous
#include <cuda_runtime.h>
#include <math.h>

#define B 64
#define T 512
#define E 256
#define U 256
#define Z 1024      /* 4*U */
#define CHUNK 64
#define NCHUNK (T / CHUNK)   /* 8 */

__device__ __forceinline__ float sigm(float v) { return 1.0f / (1.0f + expf(-v)); }

// One CTA per (batch, 64-timestep chunk). Keras masked-LSTM semantics:
// state updates ONLY at steps where token == 0 (mask True); otherwise h/c carry
// through and out[b,t] is the carried h1. Therefore:
//   - if a chunk has no zero token at any t < t_end, its entire output block is
//     exactly the zero vector (h1 never updated) -> pure streaming zero-fill.
//   - otherwise the CTA replays the (rare) sequential LSTM itself up to t_end.
//     Sibling CTAs of the same batch duplicate this deterministically (same fp
//     ops -> identical values), so there is no inter-CTA dependency at all.
__global__ __launch_bounds__(256)
void lstm_fused_kernel(const int*   __restrict__ x,
                       const float* __restrict__ emb,
                       const float* __restrict__ k0,
                       const float* __restrict__ r0,
                       const float* __restrict__ b0,
                       const float* __restrict__ k1,
                       const float* __restrict__ r1,
                       const float* __restrict__ b1,
                       float*       __restrict__ out)
{
    const int b     = blockIdx.x >> 3;
    const int chunk = blockIdx.x & (NCHUNK - 1);
    const int t0    = chunk * CHUNK;
    const int t_end = t0 + CHUNK;
    const int j     = threadIdx.x;          // 0..255

    __shared__ int acts[T];
    __shared__ int s_cnt;

    if (j == 0) s_cnt = 0;
    __syncthreads();

    int c = 0;
    #pragma unroll
    for (int t = j; t < T; t += 256) {
        const int a = (x[b * T + t] == 0) ? 1 : 0;
        acts[t] = a;
        if (t < t_end) c += a;
    }
    if (c) atomicAdd(&s_cnt, c);
    __syncthreads();

    if (s_cnt == 0) {
        // ---------- common fast path: this chunk's output is all zeros ----------
        const float4 zv = make_float4(0.f, 0.f, 0.f, 0.f);
        float4* dst = reinterpret_cast<float4*>(out + (size_t)b * T * U + (size_t)t0 * U);
        #pragma unroll
        for (int i = 0; i < 16; i++)        // 64*256 floats = 4096 float4 / 256 thr
            dst[i * 256 + j] = zv;
        if (chunk == NCHUNK - 1) {
            // t_end == T and no active step in the whole batch -> final h == 0
            float4* hdst = reinterpret_cast<float4*>(out + (size_t)B * T * U + (size_t)b * U);
            if (j < U / 4) hdst[j] = zv;
        }
        return;
    }

    // ---------- rare general path: replay the masked LSTM up to t_end ----------
    __shared__ float h0s[U];
    __shared__ float h1s[U];
    __shared__ float zbuf[Z];
    __shared__ float embs[E];

    embs[j] = emb[j];        // embedding row of token 0
    h0s[j]  = 0.0f;
    h1s[j]  = 0.0f;
    __syncthreads();

    // Constant layer-0 x-contribution: xz = emb[0,:] @ k0 + b0.
    // Thread j owns gate-vector columns 4j..4j+3 (float4 across Z).
    float4 xz = reinterpret_cast<const float4*>(b0)[j];
    for (int e = 0; e < E; e++) {
        const float  ev = embs[e];
        const float4 kv = reinterpret_cast<const float4*>(k0 + (size_t)e * Z)[j];
        xz.x += ev * kv.x; xz.y += ev * kv.y; xz.z += ev * kv.z; xz.w += ev * kv.w;
    }
    const float4 b1v = reinterpret_cast<const float4*>(b1)[j];

    float c0 = 0.0f, c1 = 0.0f;

    for (int t = 0; t < t_end; t++) {
        if (acts[t]) {
            // ---- layer 0: z = xz + h0 @ r0 ----
            float4 z = xz;
            #pragma unroll 4
            for (int k = 0; k < U; k++) {
                const float  hv = h0s[k];
                const float4 rv = reinterpret_cast<const float4*>(r0 + (size_t)k * Z)[j];
                z.x += hv * rv.x; z.y += hv * rv.y; z.z += hv * rv.z; z.w += hv * rv.w;
            }
            reinterpret_cast<float4*>(zbuf)[j] = z;
            __syncthreads();
            {
                const float ig = sigm (zbuf[0 * U + j]);
                const float fg = sigm (zbuf[1 * U + j]);
                const float gg = tanhf(zbuf[2 * U + j]);
                const float og = sigm (zbuf[3 * U + j]);
                c0 = fg * c0 + ig * gg;
                __syncthreads();                 // h0s reads (matvec) fully done
                h0s[j] = og * tanhf(c0);
            }
            __syncthreads();

            // ---- layer 1: w = b1 + h0 @ k1 + h1 @ r1 ----
            float4 w = b1v;
            #pragma unroll 2
            for (int k = 0; k < U; k++) {
                const float  h0v = h0s[k];
                const float  h1v = h1s[k];
                const float4 kv = reinterpret_cast<const float4*>(k1 + (size_t)k * Z)[j];
                const float4 rv = reinterpret_cast<const float4*>(r1 + (size_t)k * Z)[j];
                w.x += h0v * kv.x + h1v * rv.x;
                w.y += h0v * kv.y + h1v * rv.y;
                w.z += h0v * kv.z + h1v * rv.z;
                w.w += h0v * kv.w + h1v * rv.w;
            }
            __syncthreads();                     // prior zbuf reads done
            reinterpret_cast<float4*>(zbuf)[j] = w;
            __syncthreads();
            {
                const float ig = sigm (zbuf[0 * U + j]);
                const float fg = sigm (zbuf[1 * U + j]);
                const float gg = tanhf(zbuf[2 * U + j]);
                const float og = sigm (zbuf[3 * U + j]);
                c1 = fg * c1 + ig * gg;
                __syncthreads();                 // h1s reads (matvec) fully done
                h1s[j] = og * tanhf(c1);
            }
            __syncthreads();
        }
        if (t >= t0)
            out[(size_t)b * T * U + (size_t)t * U + j] = h1s[j];
    }

    if (chunk == NCHUNK - 1)                     // ran the full sequence
        out[(size_t)B * T * U + (size_t)b * U + j] = h1s[j];
}

extern "C" void kernel_launch(void* const* d_in, const int* in_sizes, int n_in,
                              void* d_out, int out_size)
{
    const int*   x   = (const int*)  d_in[0];
    const float* emb = (const float*)d_in[1];
    const float* k0  = (const float*)d_in[2];
    const float* r0  = (const float*)d_in[3];
    const float* b0  = (const float*)d_in[4];
    const float* k1  = (const float*)d_in[5];
    const float* r1  = (const float*)d_in[6];
    const float* b1  = (const float*)d_in[7];
    float* out = (float*)d_out;

    lstm_fused_kernel<<<B * NCHUNK, 256>>>(x, emb, k0, r0, b0, k1, r1, b1, out);
}